// round 15
// baseline (speedup 1.0000x reference)
#include <cuda_runtime.h>
#include <stdint.h>

#define N_NODESC 50000
#define N_EDGESC 800000
#define N_GRAPHSC 64
#define HIDC 128
#define OUTC 16
#define SCAN_T 1024

// ---------------- scratch (device globals; no allocation allowed) ----------------
__device__ int   g_is64;
__device__ int   g_deg [N_NODESC];          // degree incl. self-loop
__device__ float g_dis [N_NODESC];
__device__ int   g_roff[N_NODESC + 1];      // CSR row offsets (in-edges, excl self)
__device__ int   g_cur [N_NODESC];          // fill cursors
__device__ int   g_csrc[N_EDGESC];          // CSR column (src) indices
__device__ float g_hs  [(size_t)N_NODESC * HIDC];  // GEMM output (unscaled)
__device__ float g_h   [(size_t)N_NODESC * HIDC];  // layer-1 activation
__device__ float g_pool[N_GRAPHSC * HIDC];
__device__ float g_cnt [N_GRAPHSC];

__device__ __forceinline__ int load_index(const void* p, long long i) {
    if (g_is64) return (int)((const long long*)p)[i];
    return ((const int*)p)[i];
}

__device__ __forceinline__ void red_add_v4(float* addr, float4 v) {
    asm volatile("red.global.add.v4.f32 [%0], {%1,%2,%3,%4};"
                 :: "l"(addr), "f"(v.x), "f"(v.y), "f"(v.z), "f"(v.w) : "memory");
}

__device__ __forceinline__ uint32_t f2tf32(float x) {
    uint32_t r;
    asm("cvt.rna.tf32.f32 %0, %1;" : "=r"(r) : "f"(x));
    return r;
}

__device__ __forceinline__ void mma_tf32(float c[4], const uint32_t a[4], const uint32_t b[2]) {
    asm volatile("mma.sync.aligned.m16n8k8.row.col.f32.tf32.tf32.f32 "
                 "{%0,%1,%2,%3}, {%4,%5,%6,%7}, {%8,%9}, {%0,%1,%2,%3};"
                 : "+f"(c[0]), "+f"(c[1]), "+f"(c[2]), "+f"(c[3])
                 : "r"(a[0]), "r"(a[1]), "r"(a[2]), "r"(a[3]),
                   "r"(b[0]), "r"(b[1]));
}

// ---- prolog — dtype detect + deg=1 init + pool/cnt zero -------------------------
__global__ void prolog_kernel(const void* eidx, float* __restrict__ pool,
                              float* __restrict__ cnt) {
    int i = blockIdx.x * blockDim.x + threadIdx.x;
    if (i < N_NODESC) g_deg[i] = 1;                    // self-loop
    if (i < N_GRAPHSC * HIDC) pool[i] = 0.f;
    if (i < N_GRAPHSC) cnt[i] = 0.f;
    if (i == 0) {
        const long long* q = (const long long*)eidx;
        int is64 = 1;
        for (int k = 0; k < 64; k++) {
            long long v = q[k];
            if (v < 0 || v >= (long long)N_NODESC) { is64 = 0; break; }
        }
        g_is64 = is64;
    }
}

// ---- degree accumulation ---------------------------------------------------------
__global__ void deg_accum_kernel(const void* __restrict__ eidx) {
    int e = blockIdx.x * blockDim.x + threadIdx.x;
    if (e >= N_EDGESC) return;
    int dst = load_index(eidx, (long long)N_EDGESC + e);
    atomicAdd(&g_deg[dst], 1);
}

// ---- single-block exclusive scan of (deg-1) -> roff, cur ------------------------
__global__ __launch_bounds__(SCAN_T)
void scan_kernel() {
    __shared__ int part[SCAN_T];
    const int t = threadIdx.x;
    const int chunk = (N_NODESC + SCAN_T - 1) / SCAN_T;   // 49
    int beg = t * chunk;
    int end = beg + chunk; if (end > N_NODESC) end = N_NODESC;
    int s = 0;
    for (int i = beg; i < end; i++) s += g_deg[i] - 1;
    part[t] = s;
    __syncthreads();
    for (int off = 1; off < SCAN_T; off <<= 1) {
        int v = (t >= off) ? part[t - off] : 0;
        __syncthreads();
        part[t] += v;
        __syncthreads();
    }
    int base = (t == 0) ? 0 : part[t - 1];
    for (int i = beg; i < end; i++) {
        g_roff[i] = base;
        g_cur[i]  = base;
        base += g_deg[i] - 1;
    }
    if (t == SCAN_T - 1) g_roff[N_NODESC] = base;
}

// ---- tensor-core tf32 GEMM, 3xTF32 split ----------------------------------------
// C[M,128] = A[M,128] @ W[128,128], fp32-accurate via Ab*Wb + Ab*Ws + As*Wb.
// Block: 256 thr / 8 warps, tile 128x128, k-chunk 16. Warp tile 32x64.
__global__ __launch_bounds__(256)
void gemm_tf32_kernel(const float* __restrict__ A, const float* __restrict__ W,
                      float* __restrict__ C, int M) {
    // A pitch 20: bank(20g+t) covers all 32 banks; B pitch 136 (==8 mod 32): 8t+g.
    __shared__ float Abig[128][20], Asml[128][20];
    __shared__ float Bbig[16][136], Bsml[16][136];

    const int tid    = threadIdx.x;
    const int wid    = tid >> 5;
    const int lane   = tid & 31;
    const int g      = lane >> 2;      // 0..7
    const int t      = lane & 3;       // 0..3
    const int warp_m = wid >> 1;       // 0..3
    const int warp_n = wid & 1;        // 0..1
    const int row0   = blockIdx.x * 128;
    const int m_base = warp_m * 32;
    const int n_base = warp_n * 64;

    float c[2][8][4];
#pragma unroll
    for (int ma = 0; ma < 2; ma++)
#pragma unroll
        for (int na = 0; na < 8; na++)
#pragma unroll
            for (int q = 0; q < 4; q++) c[ma][na][q] = 0.f;

    for (int k0 = 0; k0 < 128; k0 += 16) {
        // Load A chunk: 128 rows x 16 k = 512 float4, 2 per thread.
#pragma unroll
        for (int u = 0; u < 2; u++) {
            int idx = tid + u * 256;
            int r   = idx >> 2;          // 0..127
            int c4  = (idx & 3) * 4;     // 0,4,8,12
            float4 v = make_float4(0.f, 0.f, 0.f, 0.f);
            if (row0 + r < M) v = *(const float4*)(A + (size_t)(row0 + r) * 128 + k0 + c4);
            float vv[4] = {v.x, v.y, v.z, v.w};
#pragma unroll
            for (int j = 0; j < 4; j++) {
                float big = __uint_as_float(f2tf32(vv[j]));
                Abig[r][c4 + j] = big;
                Asml[r][c4 + j] = __uint_as_float(f2tf32(vv[j] - big));
            }
        }
        // Load B chunk: 16 rows x 128 n = 512 float4, 2 per thread.
#pragma unroll
        for (int u = 0; u < 2; u++) {
            int idx = tid + u * 256;
            int r   = idx >> 5;          // 0..15
            int c4  = (idx & 31) * 4;    // 0..124
            float4 v = *(const float4*)(W + (size_t)(k0 + r) * 128 + c4);
            float vv[4] = {v.x, v.y, v.z, v.w};
#pragma unroll
            for (int j = 0; j < 4; j++) {
                float big = __uint_as_float(f2tf32(vv[j]));
                Bbig[r][c4 + j] = big;
                Bsml[r][c4 + j] = __uint_as_float(f2tf32(vv[j] - big));
            }
        }
        __syncthreads();

#pragma unroll
        for (int ks = 0; ks < 16; ks += 8) {
            uint32_t ab[2][4], as[2][4], bb[8][2], bs[8][2];
#pragma unroll
            for (int ma = 0; ma < 2; ma++) {
                int r0 = m_base + ma * 16;
                ab[ma][0] = __float_as_uint(Abig[r0 + g    ][ks + t    ]);
                ab[ma][1] = __float_as_uint(Abig[r0 + g + 8][ks + t    ]);
                ab[ma][2] = __float_as_uint(Abig[r0 + g    ][ks + t + 4]);
                ab[ma][3] = __float_as_uint(Abig[r0 + g + 8][ks + t + 4]);
                as[ma][0] = __float_as_uint(Asml[r0 + g    ][ks + t    ]);
                as[ma][1] = __float_as_uint(Asml[r0 + g + 8][ks + t    ]);
                as[ma][2] = __float_as_uint(Asml[r0 + g    ][ks + t + 4]);
                as[ma][3] = __float_as_uint(Asml[r0 + g + 8][ks + t + 4]);
            }
#pragma unroll
            for (int na = 0; na < 8; na++) {
                int n0 = n_base + na * 8;
                bb[na][0] = __float_as_uint(Bbig[ks + t    ][n0 + g]);
                bb[na][1] = __float_as_uint(Bbig[ks + t + 4][n0 + g]);
                bs[na][0] = __float_as_uint(Bsml[ks + t    ][n0 + g]);
                bs[na][1] = __float_as_uint(Bsml[ks + t + 4][n0 + g]);
            }
#pragma unroll
            for (int ma = 0; ma < 2; ma++)
#pragma unroll
                for (int na = 0; na < 8; na++) {
                    mma_tf32(c[ma][na], ab[ma], bb[na]);   // big*big
                    mma_tf32(c[ma][na], ab[ma], bs[na]);   // big*small
                    mma_tf32(c[ma][na], as[ma], bb[na]);   // small*big
                }
        }
        __syncthreads();
    }

    // Epilogue: c0,c1 -> (row g, cols 2t,2t+1); c2,c3 -> row g+8.
#pragma unroll
    for (int ma = 0; ma < 2; ma++) {
        int r_lo = row0 + m_base + ma * 16 + g;
        int r_hi = r_lo + 8;
#pragma unroll
        for (int na = 0; na < 8; na++) {
            int col = n_base + na * 8 + 2 * t;
            if (r_lo < M)
                *(float2*)(C + (size_t)r_lo * 128 + col) = make_float2(c[ma][na][0], c[ma][na][1]);
            if (r_hi < M)
                *(float2*)(C + (size_t)r_hi * 128 + col) = make_float2(c[ma][na][2], c[ma][na][3]);
        }
    }
}

// ---- dis = rsqrt(deg) ------------------------------------------------------------
__global__ void dis_kernel() {
    int i = blockIdx.x * blockDim.x + threadIdx.x;
    if (i < N_NODESC) g_dis[i] = rsqrtf((float)g_deg[i]);
}

// ---- CSR fill (counting sort by dst) --------------------------------------------
__global__ void csr_fill_kernel(const void* __restrict__ eidx) {
    int e = blockIdx.x * blockDim.x + threadIdx.x;
    if (e >= N_EDGESC) return;
    int src = load_index(eidx, e);
    int dst = load_index(eidx, (long long)N_EDGESC + e);
    int pos = atomicAdd(&g_cur[dst], 1);
    g_csrc[pos] = src;
}

// ---- gather aggregation: warp per node, fused post ------------------------------
__global__ __launch_bounds__(256)
void agg_relu_kernel(const float* __restrict__ h, const float* __restrict__ b,
                     float* __restrict__ out) {
    int n    = (blockIdx.x * blockDim.x + threadIdx.x) >> 5;
    int lane = threadIdx.x & 31;
    if (n >= N_NODESC) return;
    const float4* h4 = (const float4*)h;
    float sn = g_dis[n];
    float4 self = h4[(size_t)n * 32 + lane];
    float4 acc = make_float4(self.x * sn, self.y * sn, self.z * sn, self.w * sn);
    int beg = g_roff[n], end = g_roff[n + 1];
#pragma unroll 2
    for (int e = beg; e < end; e++) {
        int s = g_csrc[e];
        float ds = g_dis[s];
        float4 v = h4[(size_t)s * 32 + lane];
        acc.x = fmaf(v.x, ds, acc.x);
        acc.y = fmaf(v.y, ds, acc.y);
        acc.z = fmaf(v.z, ds, acc.z);
        acc.w = fmaf(v.w, ds, acc.w);
    }
    float4 bb = ((const float4*)b)[lane];
    float4 r;
    r.x = fmaxf(fmaf(acc.x, sn, bb.x), 0.f);
    r.y = fmaxf(fmaf(acc.y, sn, bb.y), 0.f);
    r.z = fmaxf(fmaf(acc.z, sn, bb.z), 0.f);
    r.w = fmaxf(fmaf(acc.w, sn, bb.w), 0.f);
    ((float4*)out)[(size_t)n * 32 + lane] = r;
}

// ---- layer-2 gather fused with relu + graph pooling + count ---------------------
__global__ __launch_bounds__(256)
void agg_pool_kernel(const float* __restrict__ h, const float* __restrict__ b,
                     const void* __restrict__ batch,
                     float* __restrict__ pool, float* __restrict__ cnt) {
    int n    = (blockIdx.x * blockDim.x + threadIdx.x) >> 5;
    int lane = threadIdx.x & 31;
    if (n >= N_NODESC) return;
    const float4* h4 = (const float4*)h;
    float sn = g_dis[n];
    float4 self = h4[(size_t)n * 32 + lane];
    float4 acc = make_float4(self.x * sn, self.y * sn, self.z * sn, self.w * sn);
    int beg = g_roff[n], end = g_roff[n + 1];
#pragma unroll 2
    for (int e = beg; e < end; e++) {
        int s = g_csrc[e];
        float ds = g_dis[s];
        float4 v = h4[(size_t)s * 32 + lane];
        acc.x = fmaf(v.x, ds, acc.x);
        acc.y = fmaf(v.y, ds, acc.y);
        acc.z = fmaf(v.z, ds, acc.z);
        acc.w = fmaf(v.w, ds, acc.w);
    }
    float4 bb = ((const float4*)b)[lane];
    float4 r;
    r.x = fmaxf(fmaf(acc.x, sn, bb.x), 0.f);
    r.y = fmaxf(fmaf(acc.y, sn, bb.y), 0.f);
    r.z = fmaxf(fmaf(acc.z, sn, bb.z), 0.f);
    r.w = fmaxf(fmaf(acc.w, sn, bb.w), 0.f);
    int g = load_index(batch, n);
    red_add_v4(pool + g * HIDC + lane * 4, r);
    if (lane == 0) atomicAdd(&cnt[g], 1.f);
}

// ---- FC head --------------------------------------------------------------------
__global__ void final_kernel(const float* __restrict__ pool,
                             const float* __restrict__ cnt,
                             const float* __restrict__ Wfc,
                             const float* __restrict__ bfc,
                             float* __restrict__ out) {
    int t = threadIdx.x;
    if (t >= N_GRAPHSC * OUTC) return;
    int g = t >> 4, o = t & 15;
    float sum = 0.f;
#pragma unroll 8
    for (int c = 0; c < HIDC; c++)
        sum = fmaf(pool[g * HIDC + c], Wfc[c * OUTC + o], sum);
    float c = fmaxf(cnt[g], 1.f);
    out[g * OUTC + o] = sum / c + bfc[o];
}

// ---- launcher -------------------------------------------------------------------
extern "C" void kernel_launch(void* const* d_in, const int* in_sizes, int n_in,
                              void* d_out, int out_size) {
    const float* x    = (const float*)d_in[0];
    const void*  eidx = d_in[1];
    const void*  bat  = d_in[2];
    const float* W1   = (const float*)d_in[3];
    const float* b1   = (const float*)d_in[4];
    const float* W2   = (const float*)d_in[5];
    const float* b2   = (const float*)d_in[6];
    const float* Wfc  = (const float*)d_in[7];
    const float* bfc  = (const float*)d_in[8];
    float* out = (float*)d_out;

    void *p_hs = nullptr, *p_h = nullptr, *p_pool = nullptr, *p_cnt = nullptr;
    cudaGetSymbolAddress(&p_hs,   g_hs);
    cudaGetSymbolAddress(&p_h,    g_h);
    cudaGetSymbolAddress(&p_pool, g_pool);
    cudaGetSymbolAddress(&p_cnt,  g_cnt);
    float* hs   = (float*)p_hs;
    float* h    = (float*)p_h;
    float* pool = (float*)p_pool;
    float* cnt  = (float*)p_cnt;

    // Lazy-create side stream + fork/join events (no device memory involved;
    // identical launch pattern every call, so graph capture is deterministic).
    static cudaStream_t s_side = nullptr;
    static cudaEvent_t  s_fork = nullptr, s_join = nullptr;
    if (s_side == nullptr) {
        cudaStreamCreateWithFlags(&s_side, cudaStreamNonBlocking);
        cudaEventCreateWithFlags(&s_fork, cudaEventDisableTiming);
        cudaEventCreateWithFlags(&s_join, cudaEventDisableTiming);
    }

    const int T = 256;
    const int nodeBlocks = (N_NODESC + T - 1) / T;
    const int edgeBlocks = (N_EDGESC + T - 1) / T;
    const int warpBlocks = (int)(((long long)N_NODESC * 32 + T - 1) / T);
    const int gemmBlocks = (N_NODESC + 127) / 128;

    // Fork: CSR/normalization chain runs on s_side, concurrent with gemm1.
    cudaEventRecord(s_fork, 0);
    cudaStreamWaitEvent(s_side, s_fork, 0);

    prolog_kernel<<<nodeBlocks, T, 0, s_side>>>(eidx, pool, cnt);
    deg_accum_kernel<<<edgeBlocks, T, 0, s_side>>>(eidx);
    scan_kernel<<<1, SCAN_T, 0, s_side>>>();
    dis_kernel<<<nodeBlocks, T, 0, s_side>>>();
    csr_fill_kernel<<<edgeBlocks, T, 0, s_side>>>(eidx);
    cudaEventRecord(s_join, s_side);

    // Main stream: gemm1 (independent of the CSR chain).
    gemm_tf32_kernel<<<gemmBlocks, 256>>>(x, W1, hs, N_NODESC);

    // Join: everything below needs both gemm1 and the CSR chain.
    cudaStreamWaitEvent(0, s_join, 0);

    agg_relu_kernel<<<warpBlocks, T>>>(hs, b1, h);
    gemm_tf32_kernel<<<gemmBlocks, 256>>>(h, W2, hs, N_NODESC);
    agg_pool_kernel<<<warpBlocks, T>>>(hs, b2, bat, pool, cnt);
    final_kernel<<<1, 1024>>>(pool, cnt, Wfc, bfc, out);
}